// round 6
// baseline (speedup 1.0000x reference)
#include <cuda_runtime.h>
#include <cuda_bf16.h>
#include <math.h>
#include <stdint.h>

#define NTOK 4096   // B*T
#define DDIM 1024
#define FDIM 4096
#define NEXP 8
#define NROWS (NTOK * 2)   // dispatch rows (top-2)

#define KCH 32
#define APITCH 80          // 32 bf16 = 64B data padded to 80B (odd # of 16B units)

// ---------------- device scratch (R5-sized footprint: ~168MB) -------------
__device__ int   g_count[NEXP];
__device__ int   g_cursor[NEXP];
__device__ int   g_offset[NEXP];
__device__ int   g_topk_idx[NTOK * 2];
__device__ float g_topk_w[NTOK * 2];
__device__ int   g_token_of_row[NROWS];
__device__ float g_w_of_row[NROWS];
__device__ int   g_row_of_token[NROWS];
__device__ __align__(16) float g_H[(size_t)NROWS * FDIM];   // 134 MB fp32
__device__ __align__(16) float g_Y[(size_t)NROWS * DDIM];   // 33.5 MB fp32

// ---------------- helpers ----------------
__device__ __forceinline__ uint32_t smem_u32(const void* p) {
    uint32_t a;
    asm("{ .reg .u64 t; cvta.to.shared.u64 t, %1; cvt.u32.u64 %0, t; }" : "=r"(a) : "l"(p));
    return a;
}
__device__ __forceinline__ void ldm_x4(uint32_t (&r)[4], uint32_t a) {
    asm volatile("ldmatrix.sync.aligned.m8n8.x4.shared.b16 {%0,%1,%2,%3}, [%4];"
                 : "=r"(r[0]), "=r"(r[1]), "=r"(r[2]), "=r"(r[3]) : "r"(a));
}
__device__ __forceinline__ void ldm_x4t(uint32_t (&r)[4], uint32_t a) {
    asm volatile("ldmatrix.sync.aligned.m8n8.x4.trans.shared.b16 {%0,%1,%2,%3}, [%4];"
                 : "=r"(r[0]), "=r"(r[1]), "=r"(r[2]), "=r"(r[3]) : "r"(a));
}
__device__ __forceinline__ void mma16816(float (&d)[4], const uint32_t (&a)[4],
                                         uint32_t b0, uint32_t b1) {
    asm volatile("mma.sync.aligned.m16n8k16.row.col.f32.bf16.bf16.f32 "
                 "{%0,%1,%2,%3}, {%4,%5,%6,%7}, {%8,%9}, {%0,%1,%2,%3};"
                 : "+f"(d[0]), "+f"(d[1]), "+f"(d[2]), "+f"(d[3])
                 : "r"(a[0]), "r"(a[1]), "r"(a[2]), "r"(a[3]), "r"(b0), "r"(b1));
}
__device__ __forceinline__ uint32_t pk2(__nv_bfloat16 a, __nv_bfloat16 b) {
    return (uint32_t)__bfloat16_as_ushort(a) | ((uint32_t)__bfloat16_as_ushort(b) << 16);
}
__device__ __forceinline__ float gelu_exact(float v) {
    return 0.5f * v * (1.0f + erff(v * 0.70710678118654752440f));
}
__device__ __forceinline__ void split8(float4 v0, float4 v1, uint4& hi, uint4& lo) {
    __nv_bfloat16 h0 = __float2bfloat16(v0.x), h1 = __float2bfloat16(v0.y);
    __nv_bfloat16 h2 = __float2bfloat16(v0.z), h3 = __float2bfloat16(v0.w);
    __nv_bfloat16 h4 = __float2bfloat16(v1.x), h5 = __float2bfloat16(v1.y);
    __nv_bfloat16 h6 = __float2bfloat16(v1.z), h7 = __float2bfloat16(v1.w);
    hi.x = pk2(h0, h1); hi.y = pk2(h2, h3); hi.z = pk2(h4, h5); hi.w = pk2(h6, h7);
    lo.x = pk2(__float2bfloat16(v0.x - __bfloat162float(h0)),
               __float2bfloat16(v0.y - __bfloat162float(h1)));
    lo.y = pk2(__float2bfloat16(v0.z - __bfloat162float(h2)),
               __float2bfloat16(v0.w - __bfloat162float(h3)));
    lo.z = pk2(__float2bfloat16(v1.x - __bfloat162float(h4)),
               __float2bfloat16(v1.y - __bfloat162float(h5)));
    lo.w = pk2(__float2bfloat16(v1.z - __bfloat162float(h6)),
               __float2bfloat16(v1.w - __bfloat162float(h7)));
}

// ---------------- K0-K3: routing (unchanged, proven) ----------------
__global__ void zero_kernel() {
    int t = threadIdx.x;
    if (t < NEXP) { g_count[t] = 0; g_cursor[t] = 0; }
}

__global__ void router_kernel(const float* __restrict__ x,
                              const float* __restrict__ Wr) {
    int gwarp  = (blockIdx.x * blockDim.x + threadIdx.x) >> 5;
    int lane   = threadIdx.x & 31;
    int nwarps = (gridDim.x * blockDim.x) >> 5;
    for (int n = gwarp; n < NTOK; n += nwarps) {
        const float* xr = x + (size_t)n * DDIM;
        float acc[NEXP];
        #pragma unroll
        for (int e = 0; e < NEXP; e++) acc[e] = 0.f;
        for (int d = lane; d < DDIM; d += 32) {
            float xv = xr[d];
            const float* wr = Wr + (size_t)d * NEXP;
            float4 w0 = *(const float4*)(wr);
            float4 w1 = *(const float4*)(wr + 4);
            acc[0] = fmaf(xv, w0.x, acc[0]); acc[1] = fmaf(xv, w0.y, acc[1]);
            acc[2] = fmaf(xv, w0.z, acc[2]); acc[3] = fmaf(xv, w0.w, acc[3]);
            acc[4] = fmaf(xv, w1.x, acc[4]); acc[5] = fmaf(xv, w1.y, acc[5]);
            acc[6] = fmaf(xv, w1.z, acc[6]); acc[7] = fmaf(xv, w1.w, acc[7]);
        }
        #pragma unroll
        for (int e = 0; e < NEXP; e++)
            #pragma unroll
            for (int o = 16; o > 0; o >>= 1)
                acc[e] += __shfl_xor_sync(0xFFFFFFFFu, acc[e], o);
        if (lane == 0) {
            int i0 = 0; float v0 = acc[0];
            #pragma unroll
            for (int e = 1; e < NEXP; e++)
                if (acc[e] > v0) { v0 = acc[e]; i0 = e; }
            int i1 = -1; float v1 = -3.4e38f;
            #pragma unroll
            for (int e = 0; e < NEXP; e++)
                if (e != i0 && acc[e] > v1) { v1 = acc[e]; i1 = e; }
            float e1 = __expf(v1 - v0);
            float inv = 1.0f / (1.0f + e1);
            g_topk_idx[2 * n + 0] = i0;
            g_topk_idx[2 * n + 1] = i1;
            g_topk_w[2 * n + 0] = inv;
            g_topk_w[2 * n + 1] = e1 * inv;
            atomicAdd(&g_count[i0], 1);
            atomicAdd(&g_count[i1], 1);
        }
    }
}

__global__ void prefix_kernel() {
    int s = 0;
    for (int e = 0; e < NEXP; e++) { g_offset[e] = s; s += g_count[e]; }
}

__global__ void dispatch_kernel() {
    int n = blockIdx.x * blockDim.x + threadIdx.x;
    if (n >= NTOK) return;
    #pragma unroll
    for (int s = 0; s < 2; s++) {
        int e   = g_topk_idx[2 * n + s];
        int pos = atomicAdd(&g_cursor[e], 1);
        int row = g_offset[e] + pos;
        g_token_of_row[row] = n;
        g_w_of_row[row]     = g_topk_w[2 * n + s];
        g_row_of_token[2 * n + s] = row;
    }
}

// ---------------- GEMM: split-bf16 mma.sync, 512 threads ----------------
// PH1: 128x256 tile, H = gelu(gather(X) @ W1[e]); PH2: 128x128, Y = w*(H @ W2[e])
template<bool PH1>
__global__ __launch_bounds__(512) void moe_gemm_kernel(const float* __restrict__ Aglob,
                                                       const float* __restrict__ Wglob) {
    constexpr int K   = PH1 ? DDIM : FDIM;
    constexpr int NT  = PH1 ? FDIM : DDIM;
    constexpr int BN  = PH1 ? 256 : 128;
    constexpr int NC  = K / KCH;
    constexpr int NI  = BN / 32;               // n8-blocks per warp (8 or 4)
    constexpr int NP  = NI / 2;                // ldm_x4t pairs per warp (4 or 2)
    constexpr int BPITCH = BN * 2 + 16;        // 528 or 272 (odd # of 16B units)
    constexpr int A_TILE = 128 * APITCH;       // 10240
    constexpr int B_TILE = KCH * BPITCH;       // 16896 or 8704
    constexpr int STAGE  = 2 * A_TILE + 2 * B_TILE;
    constexpr int BSEG   = BN / 8;             // 8-elem segs per B row (32 or 16)
    constexpr int BITER  = (KCH * BSEG) / 512; // B load iterations (2 or 1)

    const int e   = blockIdx.z;
    const int cnt = g_count[e];
    const int m0  = blockIdx.x * 128;
    if (m0 >= cnt) return;
    const int n0  = blockIdx.y * BN;
    const int off = g_offset[e];
    const size_t rowbase = (size_t)off + m0;
    const float* Bsrc = Wglob + (size_t)e * K * NT + n0;

    extern __shared__ __align__(128) char smbuf[];   // 2 * STAGE
    __shared__ int   toks[128];
    __shared__ float wrow[128];

    const int tid  = threadIdx.x;
    const int warp = tid >> 5, lane = tid & 31;
    const int wm = warp & 3, wn = warp >> 2;   // 4x4 warps: 32m x (BN/4)n each

    if (tid < 128) {
        int r = m0 + tid;
        if (PH1) toks[tid] = (r < cnt) ? g_token_of_row[off + r] : g_token_of_row[off];
        else     wrow[tid] = (r < cnt) ? g_w_of_row[off + r] : 0.f;
    }
    __syncthreads();

    // loader roles
    const int a_row = tid >> 2, a_seg = tid & 3;       // 128 rows x 4 segs(8 elems)
    const int b_k0  = tid / BSEG, b_seg = tid % BSEG;  // + i*(512/BSEG) rows
    const float* aptr;
    if (PH1) {
        aptr = Aglob + (size_t)toks[a_row] * DDIM;
    } else {
        size_t ra = rowbase + a_row;
        if (ra >= NROWS) ra = 0;
        aptr = Aglob + ra * (size_t)FDIM;
    }

    float4 pa0, pa1, pb0[BITER], pb1[BITER];
    auto prefetch = [&](int kc) {
        pa0 = *(const float4*)(aptr + kc + a_seg * 8);
        pa1 = *(const float4*)(aptr + kc + a_seg * 8 + 4);
        #pragma unroll
        for (int i = 0; i < BITER; i++) {
            int bk = b_k0 + i * (512 / BSEG);
            pb0[i] = *(const float4*)(Bsrc + (size_t)(kc + bk) * NT + b_seg * 8);
            pb1[i] = *(const float4*)(Bsrc + (size_t)(kc + bk) * NT + b_seg * 8 + 4);
        }
    };
    auto store_stage = [&](int stg) {
        char* dst = smbuf + stg * STAGE;
        uint4 hi, lo;
        split8(pa0, pa1, hi, lo);
        *(uint4*)(dst + a_row * APITCH + a_seg * 16) = hi;
        *(uint4*)(dst + A_TILE + a_row * APITCH + a_seg * 16) = lo;
        #pragma unroll
        for (int i = 0; i < BITER; i++) {
            int bk = b_k0 + i * (512 / BSEG);
            split8(pb0[i], pb1[i], hi, lo);
            *(uint4*)(dst + 2 * A_TILE + bk * BPITCH + b_seg * 16) = hi;
            *(uint4*)(dst + 2 * A_TILE + B_TILE + bk * BPITCH + b_seg * 16) = lo;
        }
    };

    prefetch(0);
    store_stage(0);
    __syncthreads();

    float acc[2][NI][4];
    #pragma unroll
    for (int i = 0; i < 2; i++)
        #pragma unroll
        for (int j = 0; j < NI; j++)
            #pragma unroll
            for (int q = 0; q < 4; q++) acc[i][j][q] = 0.f;

    const uint32_t smb = smem_u32(smbuf);
    const int lrow = lane & 15;
    const int lk   = lane >> 4;
    const uint32_t aoff = (uint32_t)((wm * 32 + lrow) * APITCH + lk * 16);
    const uint32_t boff = (uint32_t)(2 * A_TILE + lrow * BPITCH + wn * (BN / 4) * 2 + lk * 16);

    #pragma unroll 1
    for (int c = 0; c < NC; c++) {
        if (c + 1 < NC) prefetch((c + 1) * KCH);   // LDG overlaps MMAs below

        uint32_t stb = smb + (uint32_t)((c & 1) * STAGE);
        #pragma unroll
        for (int ksub = 0; ksub < 2; ksub++) {
            uint32_t bh[NP][4], bl[NP][4];
            #pragma unroll
            for (int p = 0; p < NP; p++) {
                uint32_t b = stb + boff + (uint32_t)(ksub * 16 * BPITCH) + p * 32;
                ldm_x4t(bh[p], b);
                ldm_x4t(bl[p], b + B_TILE);
            }
            #pragma unroll
            for (int mi = 0; mi < 2; mi++) {
                uint32_t ah[4], al[4];
                uint32_t a = stb + aoff + (uint32_t)(mi * 16 * APITCH) + ksub * 32;
                ldm_x4(ah, a);
                ldm_x4(al, a + A_TILE);
                #pragma unroll
                for (int ni = 0; ni < NI; ni++) {
                    int p = ni >> 1, q = (ni & 1) * 2;
                    mma16816(acc[mi][ni], ah, bh[p][q], bh[p][q + 1]);
                    mma16816(acc[mi][ni], ah, bl[p][q], bl[p][q + 1]);
                    mma16816(acc[mi][ni], al, bh[p][q], bh[p][q + 1]);
                }
            }
        }
        __syncthreads();
        if (c + 1 < NC) store_stage((c + 1) & 1);
        __syncthreads();
    }

    // ---------------- epilogue ----------------
    const int ro  = lane >> 2;
    const int cp2 = (lane & 3) * 2;
    #pragma unroll
    for (int mi = 0; mi < 2; mi++)
        #pragma unroll
        for (int half = 0; half < 2; half++) {
            int lr = wm * 32 + mi * 16 + half * 8 + ro;
            if (m0 + lr < cnt) {
                size_t gr = rowbase + lr;
                if (PH1) {
                    float* od = g_H + gr * (size_t)FDIM + n0 + wn * (BN / 4) + cp2;
                    #pragma unroll
                    for (int ni = 0; ni < NI; ni++) {
                        float2 v;
                        v.x = gelu_exact(acc[mi][ni][half * 2 + 0]);
                        v.y = gelu_exact(acc[mi][ni][half * 2 + 1]);
                        *(float2*)(od + ni * 8) = v;
                    }
                } else {
                    float w = wrow[lr];
                    float* od = g_Y + gr * (size_t)DDIM + n0 + wn * (BN / 4) + cp2;
                    #pragma unroll
                    for (int ni = 0; ni < NI; ni++) {
                        float2 v;
                        v.x = w * acc[mi][ni][half * 2 + 0];
                        v.y = w * acc[mi][ni][half * 2 + 1];
                        *(float2*)(od + ni * 8) = v;
                    }
                }
            }
        }
}

// ---------------- combine ----------------
__global__ void combine_kernel(float* __restrict__ out) {
    int idx = blockIdx.x * blockDim.x + threadIdx.x;
    if (idx >= NTOK * (DDIM / 4)) return;
    int n  = idx >> 8;
    int d4 = idx & 255;
    int r0 = g_row_of_token[2 * n + 0];
    int r1 = g_row_of_token[2 * n + 1];
    float4 a = *(const float4*)(g_Y + (size_t)r0 * DDIM + d4 * 4);
    float4 b = *(const float4*)(g_Y + (size_t)r1 * DDIM + d4 * 4);
    float4 o;
    o.x = a.x + b.x; o.y = a.y + b.y; o.z = a.z + b.z; o.w = a.w + b.w;
    ((float4*)out)[idx] = o;
}

// ---------------- launch ----------------
extern "C" void kernel_launch(void* const* d_in, const int* in_sizes, int n_in,
                              void* d_out, int out_size) {
    const float* x  = (const float*)d_in[0];
    const float* Wr = (const float*)d_in[1];
    const float* W1 = (const float*)d_in[2];   // [E][D][F]
    const float* W2 = (const float*)d_in[3];   // [E][F][D]
    float* out = (float*)d_out;

    // dynamic smem sizes: PH1 stage = 2*10240 + 2*16896 = 54272 -> 108544
    //                     PH2 stage = 2*10240 + 2*8704  = 37888 -> 75776
    const int smem1 = 2 * (2 * 128 * APITCH + 2 * KCH * (256 * 2 + 16));
    const int smem2 = 2 * (2 * 128 * APITCH + 2 * KCH * (128 * 2 + 16));
    static bool attr_done = false;
    if (!attr_done) {
        cudaFuncSetAttribute(moe_gemm_kernel<true>,
                             cudaFuncAttributeMaxDynamicSharedMemorySize, smem1);
        cudaFuncSetAttribute(moe_gemm_kernel<false>,
                             cudaFuncAttributeMaxDynamicSharedMemorySize, smem2);
        attr_done = true;
    }

    zero_kernel<<<1, 32>>>();
    router_kernel<<<64, 256>>>(x, Wr);
    prefix_kernel<<<1, 1>>>();
    dispatch_kernel<<<(NTOK + 255) / 256, 256>>>();

    float* hptr = nullptr;
    cudaGetSymbolAddress((void**)&hptr, g_H);
    moe_gemm_kernel<true><<<dim3(NROWS / 128, FDIM / 256, NEXP), 512, smem1>>>(x, W1);
    moe_gemm_kernel<false><<<dim3(NROWS / 128, DDIM / 128, NEXP), 512, smem2>>>(hptr, W2);
    combine_kernel<<<(NTOK * (DDIM / 4) + 255) / 256, 256>>>(out);
}

// round 7
// speedup vs baseline: 1.4258x; 1.4258x over previous
#include <cuda_runtime.h>
#include <cuda_bf16.h>
#include <math.h>
#include <stdint.h>

#define NTOK 4096   // B*T
#define DDIM 1024
#define FDIM 4096
#define NEXP 8
#define NROWS (NTOK * 2)   // dispatch rows (top-2)

#define KCH 32
#define APITCH 80                        // 32 bf16 = 64B padded to 80B (odd 16B units)
#define BPITCH 272                       // 128 bf16 = 256B padded to 272B
#define A_TILE (128 * APITCH)            // 10240 per half
#define B_TILE (KCH * BPITCH)            // 8704 per half
#define STAGE  (2 * A_TILE + 2 * B_TILE) // 37888
#define SMEM_BYTES (2 * STAGE)           // 75776 (dynamic, opt-in)

// ---------------- device scratch (~162MB total) ----------------
__device__ int   g_count[NEXP];
__device__ int   g_cursor[NEXP];
__device__ int   g_offset[NEXP];
__device__ int   g_topk_idx[NTOK * 2];
__device__ float g_topk_w[NTOK * 2];
__device__ int   g_token_of_row[NROWS];
__device__ float g_w_of_row[NROWS];
__device__ int   g_row_of_token[NROWS];
__device__ __align__(16) __nv_bfloat16 g_Hhi[(size_t)NROWS * FDIM];  // 64 MB
__device__ __align__(16) __nv_bfloat16 g_Hlo[(size_t)NROWS * FDIM];  // 64 MB
__device__ __align__(16) float         g_Y[(size_t)NROWS * DDIM];    // 33.5 MB

// ---------------- helpers ----------------
__device__ __forceinline__ uint32_t smem_u32(const void* p) {
    uint32_t a;
    asm("{ .reg .u64 t; cvta.to.shared.u64 t, %1; cvt.u32.u64 %0, t; }" : "=r"(a) : "l"(p));
    return a;
}
__device__ __forceinline__ void ldm_x4(uint32_t (&r)[4], uint32_t a) {
    asm volatile("ldmatrix.sync.aligned.m8n8.x4.shared.b16 {%0,%1,%2,%3}, [%4];"
                 : "=r"(r[0]), "=r"(r[1]), "=r"(r[2]), "=r"(r[3]) : "r"(a));
}
__device__ __forceinline__ void ldm_x4t(uint32_t (&r)[4], uint32_t a) {
    asm volatile("ldmatrix.sync.aligned.m8n8.x4.trans.shared.b16 {%0,%1,%2,%3}, [%4];"
                 : "=r"(r[0]), "=r"(r[1]), "=r"(r[2]), "=r"(r[3]) : "r"(a));
}
__device__ __forceinline__ void mma16816(float (&d)[4], const uint32_t (&a)[4],
                                         uint32_t b0, uint32_t b1) {
    asm volatile("mma.sync.aligned.m16n8k16.row.col.f32.bf16.bf16.f32 "
                 "{%0,%1,%2,%3}, {%4,%5,%6,%7}, {%8,%9}, {%0,%1,%2,%3};"
                 : "+f"(d[0]), "+f"(d[1]), "+f"(d[2]), "+f"(d[3])
                 : "r"(a[0]), "r"(a[1]), "r"(a[2]), "r"(a[3]), "r"(b0), "r"(b1));
}
__device__ __forceinline__ uint32_t pk2(__nv_bfloat16 a, __nv_bfloat16 b) {
    return (uint32_t)__bfloat16_as_ushort(a) | ((uint32_t)__bfloat16_as_ushort(b) << 16);
}
__device__ __forceinline__ float gelu_exact(float v) {
    return 0.5f * v * (1.0f + erff(v * 0.70710678118654752440f));
}
__device__ __forceinline__ void split8(float4 v0, float4 v1, uint4& hi, uint4& lo) {
    __nv_bfloat16 h0 = __float2bfloat16(v0.x), h1 = __float2bfloat16(v0.y);
    __nv_bfloat16 h2 = __float2bfloat16(v0.z), h3 = __float2bfloat16(v0.w);
    __nv_bfloat16 h4 = __float2bfloat16(v1.x), h5 = __float2bfloat16(v1.y);
    __nv_bfloat16 h6 = __float2bfloat16(v1.z), h7 = __float2bfloat16(v1.w);
    hi.x = pk2(h0, h1); hi.y = pk2(h2, h3); hi.z = pk2(h4, h5); hi.w = pk2(h6, h7);
    lo.x = pk2(__float2bfloat16(v0.x - __bfloat162float(h0)),
               __float2bfloat16(v0.y - __bfloat162float(h1)));
    lo.y = pk2(__float2bfloat16(v0.z - __bfloat162float(h2)),
               __float2bfloat16(v0.w - __bfloat162float(h3)));
    lo.z = pk2(__float2bfloat16(v1.x - __bfloat162float(h4)),
               __float2bfloat16(v1.y - __bfloat162float(h5)));
    lo.w = pk2(__float2bfloat16(v1.z - __bfloat162float(h6)),
               __float2bfloat16(v1.w - __bfloat162float(h7)));
}

// ---------------- K0-K3: routing (unchanged, proven) ----------------
__global__ void zero_kernel() {
    int t = threadIdx.x;
    if (t < NEXP) { g_count[t] = 0; g_cursor[t] = 0; }
}

__global__ void router_kernel(const float* __restrict__ x,
                              const float* __restrict__ Wr) {
    int gwarp  = (blockIdx.x * blockDim.x + threadIdx.x) >> 5;
    int lane   = threadIdx.x & 31;
    int nwarps = (gridDim.x * blockDim.x) >> 5;
    for (int n = gwarp; n < NTOK; n += nwarps) {
        const float* xr = x + (size_t)n * DDIM;
        float acc[NEXP];
        #pragma unroll
        for (int e = 0; e < NEXP; e++) acc[e] = 0.f;
        for (int d = lane; d < DDIM; d += 32) {
            float xv = xr[d];
            const float* wr = Wr + (size_t)d * NEXP;
            float4 w0 = *(const float4*)(wr);
            float4 w1 = *(const float4*)(wr + 4);
            acc[0] = fmaf(xv, w0.x, acc[0]); acc[1] = fmaf(xv, w0.y, acc[1]);
            acc[2] = fmaf(xv, w0.z, acc[2]); acc[3] = fmaf(xv, w0.w, acc[3]);
            acc[4] = fmaf(xv, w1.x, acc[4]); acc[5] = fmaf(xv, w1.y, acc[5]);
            acc[6] = fmaf(xv, w1.z, acc[6]); acc[7] = fmaf(xv, w1.w, acc[7]);
        }
        #pragma unroll
        for (int e = 0; e < NEXP; e++)
            #pragma unroll
            for (int o = 16; o > 0; o >>= 1)
                acc[e] += __shfl_xor_sync(0xFFFFFFFFu, acc[e], o);
        if (lane == 0) {
            int i0 = 0; float v0 = acc[0];
            #pragma unroll
            for (int e = 1; e < NEXP; e++)
                if (acc[e] > v0) { v0 = acc[e]; i0 = e; }
            int i1 = -1; float v1 = -3.4e38f;
            #pragma unroll
            for (int e = 0; e < NEXP; e++)
                if (e != i0 && acc[e] > v1) { v1 = acc[e]; i1 = e; }
            float e1 = __expf(v1 - v0);
            float inv = 1.0f / (1.0f + e1);
            g_topk_idx[2 * n + 0] = i0;
            g_topk_idx[2 * n + 1] = i1;
            g_topk_w[2 * n + 0] = inv;
            g_topk_w[2 * n + 1] = e1 * inv;
            atomicAdd(&g_count[i0], 1);
            atomicAdd(&g_count[i1], 1);
        }
    }
}

__global__ void prefix_kernel() {
    int s = 0;
    for (int e = 0; e < NEXP; e++) { g_offset[e] = s; s += g_count[e]; }
}

__global__ void dispatch_kernel() {
    int n = blockIdx.x * blockDim.x + threadIdx.x;
    if (n >= NTOK) return;
    #pragma unroll
    for (int s = 0; s < 2; s++) {
        int e   = g_topk_idx[2 * n + s];
        int pos = atomicAdd(&g_cursor[e], 1);
        int row = g_offset[e] + pos;
        g_token_of_row[row] = n;
        g_w_of_row[row]     = g_topk_w[2 * n + s];
        g_row_of_token[2 * n + s] = row;
    }
}

// ---------------- GEMM: split-bf16 mma.sync, 256 thr, KCH=32, 1 sync/chunk
// PH1: H(bf16 hi/lo) = gelu(gather(X) @ W1[e]); PH2: Y = w * (H @ W2[e])
template<bool PH1>
__global__ __launch_bounds__(256) void moe_gemm_kernel(const float* __restrict__ Xglob,
                                                       const float* __restrict__ Wglob) {
    constexpr int K  = PH1 ? DDIM : FDIM;
    constexpr int NT = PH1 ? FDIM : DDIM;
    constexpr int NC = K / KCH;

    const int e   = blockIdx.z;
    const int cnt = g_count[e];
    const int m0  = blockIdx.x * 128;
    if (m0 >= cnt) return;
    const int n0  = blockIdx.y * 128;
    const int off = g_offset[e];
    const size_t rowbase = (size_t)off + m0;
    const float* Bsrc = Wglob + (size_t)e * K * NT + n0;

    extern __shared__ __align__(128) char smbuf[];
    __shared__ int   toks[128];
    __shared__ float wrow[128];

    const int tid  = threadIdx.x;
    const int warp = tid >> 5, lane = tid & 31;
    const int wm = warp & 1, wn = warp >> 1;    // 2x4 warps: 64m x 32n each

    if (tid < 128) {
        int r = m0 + tid;
        if (PH1) toks[tid] = (r < cnt) ? g_token_of_row[off + r] : g_token_of_row[off];
        else     wrow[tid] = (r < cnt) ? g_w_of_row[off + r] : 0.f;
    }
    __syncthreads();

    // loader roles: A 128 rows x 2 segs(16 elems); B 32 k-rows x 8 segs(16 elems)
    const int a_row = tid >> 1, a_seg = tid & 1;
    const int b_k   = tid >> 3, b_seg = tid & 7;

    const float* aptrF = nullptr;
    const __nv_bfloat16 *aptrH = nullptr, *aptrL = nullptr;
    if (PH1) {
        aptrF = Xglob + (size_t)toks[a_row] * DDIM;
    } else {
        size_t ra = rowbase + a_row;
        if (ra >= NROWS) ra = 0;
        aptrH = g_Hhi + ra * (size_t)FDIM;
        aptrL = g_Hlo + ra * (size_t)FDIM;
    }

    // prefetch registers
    float4 pa[4];          // PH1 only: 16 fp32 of A
    uint4  pah, pal;       // PH2 only: 16 bf16 hi + lo of A
    float4 pb[4];          // 16 fp32 of B

    auto prefetch = [&](int kc) {
        if (PH1) {
            const float* s = aptrF + kc + a_seg * 16;
            pa[0] = *(const float4*)(s + 0);
            pa[1] = *(const float4*)(s + 4);
            pa[2] = *(const float4*)(s + 8);
            pa[3] = *(const float4*)(s + 12);
        } else {
            pah = *(const uint4*)(aptrH + kc + a_seg * 16);
            pal = *(const uint4*)(aptrL + kc + a_seg * 16);
        }
        const float* sb = Bsrc + (size_t)(kc + b_k) * NT + b_seg * 16;
        pb[0] = *(const float4*)(sb + 0);
        pb[1] = *(const float4*)(sb + 4);
        pb[2] = *(const float4*)(sb + 8);
        pb[3] = *(const float4*)(sb + 12);
    };
    auto store_stage = [&](int stg) {
        char* dst = smbuf + stg * STAGE;
        uint4 hi, lo;
        if (PH1) {
            split8(pa[0], pa[1], hi, lo);
            *(uint4*)(dst + a_row * APITCH + a_seg * 32) = hi;
            *(uint4*)(dst + A_TILE + a_row * APITCH + a_seg * 32) = lo;
            split8(pa[2], pa[3], hi, lo);
            *(uint4*)(dst + a_row * APITCH + a_seg * 32 + 16) = hi;
            *(uint4*)(dst + A_TILE + a_row * APITCH + a_seg * 32 + 16) = lo;
        } else {
            *(uint4*)(dst + a_row * APITCH + a_seg * 32) = pah;
            *(uint4*)(dst + A_TILE + a_row * APITCH + a_seg * 32) = pal;
            // a_seg covers 16 elems = 32B: one uint4 is 16B; need both halves:
        }
        split8(pb[0], pb[1], hi, lo);
        *(uint4*)(dst + 2 * A_TILE + b_k * BPITCH + b_seg * 32) = hi;
        *(uint4*)(dst + 2 * A_TILE + B_TILE + b_k * BPITCH + b_seg * 32) = lo;
        split8(pb[2], pb[3], hi, lo);
        *(uint4*)(dst + 2 * A_TILE + b_k * BPITCH + b_seg * 32 + 16) = hi;
        *(uint4*)(dst + 2 * A_TILE + B_TILE + b_k * BPITCH + b_seg * 32 + 16) = lo;
    };

    // NOTE for PH2: a_seg covers 16 bf16 = 32B, but uint4 = 16B. Load/store both.
    uint4 pah2, pal2;
    auto prefetch2 = [&](int kc) {
        if (!PH1) {
            pah2 = *(const uint4*)(aptrH + kc + a_seg * 16 + 8);
            pal2 = *(const uint4*)(aptrL + kc + a_seg * 16 + 8);
        }
    };
    auto store_stage2 = [&](int stg) {
        if (!PH1) {
            char* dst = smbuf + stg * STAGE;
            *(uint4*)(dst + a_row * APITCH + a_seg * 32 + 16) = pah2;
            *(uint4*)(dst + A_TILE + a_row * APITCH + a_seg * 32 + 16) = pal2;
        }
    };

    prefetch(0); prefetch2(0);
    store_stage(0); store_stage2(0);

    float acc[4][4][4];
    #pragma unroll
    for (int i = 0; i < 4; i++)
        #pragma unroll
        for (int j = 0; j < 4; j++)
            #pragma unroll
            for (int q = 0; q < 4; q++) acc[i][j][q] = 0.f;

    const uint32_t smb = smem_u32(smbuf);
    const int lrow = lane & 15;
    const int lk   = lane >> 4;
    const uint32_t aoff = (uint32_t)((wm * 64 + lrow) * APITCH + lk * 16);
    const uint32_t boff = (uint32_t)(2 * A_TILE + lrow * BPITCH + wn * 64 + lk * 16);

    #pragma unroll 1
    for (int c = 0; c < NC; c++) {
        __syncthreads();                 // stage c&1 ready; stage (c+1)&1 free
        if (c + 1 < NC) { prefetch((c + 1) * KCH); prefetch2((c + 1) * KCH); }

        uint32_t stb = smb + (uint32_t)((c & 1) * STAGE);
        #pragma unroll
        for (int ksub = 0; ksub < 2; ksub++) {
            uint32_t bh[2][4], bl[2][4];
            #pragma unroll
            for (int p = 0; p < 2; p++) {
                uint32_t b = stb + boff + (uint32_t)(ksub * 16 * BPITCH) + p * 32;
                ldm_x4t(bh[p], b);
                ldm_x4t(bl[p], b + B_TILE);
            }
            #pragma unroll
            for (int mi = 0; mi < 4; mi++) {
                uint32_t ah[4], al[4];
                uint32_t a = stb + aoff + (uint32_t)(mi * 16 * APITCH) + ksub * 32;
                ldm_x4(ah, a);
                ldm_x4(al, a + A_TILE);
                #pragma unroll
                for (int ni = 0; ni < 4; ni++) {
                    int p = ni >> 1, q = (ni & 1) * 2;
                    mma16816(acc[mi][ni], ah, bh[p][q], bh[p][q + 1]);
                    mma16816(acc[mi][ni], ah, bl[p][q], bl[p][q + 1]);
                    mma16816(acc[mi][ni], al, bh[p][q], bh[p][q + 1]);
                }
            }
        }
        if (c + 1 < NC) { store_stage((c + 1) & 1); store_stage2((c + 1) & 1); }
    }

    // ---------------- epilogue ----------------
    const int ro  = lane >> 2;
    const int cp2 = (lane & 3) * 2;
    #pragma unroll
    for (int mi = 0; mi < 4; mi++)
        #pragma unroll
        for (int half = 0; half < 2; half++) {
            int lr = wm * 64 + mi * 16 + half * 8 + ro;
            if (m0 + lr < cnt) {
                size_t gr = rowbase + lr;
                if (PH1) {
                    __nv_bfloat16* oh = g_Hhi + gr * (size_t)FDIM + n0 + wn * 32 + cp2;
                    __nv_bfloat16* ol = g_Hlo + gr * (size_t)FDIM + n0 + wn * 32 + cp2;
                    #pragma unroll
                    for (int ni = 0; ni < 4; ni++) {
                        float f0 = gelu_exact(acc[mi][ni][half * 2 + 0]);
                        float f1 = gelu_exact(acc[mi][ni][half * 2 + 1]);
                        __nv_bfloat16 h0 = __float2bfloat16(f0), h1 = __float2bfloat16(f1);
                        __nv_bfloat16 l0 = __float2bfloat16(f0 - __bfloat162float(h0));
                        __nv_bfloat16 l1 = __float2bfloat16(f1 - __bfloat162float(h1));
                        *(uint32_t*)(oh + ni * 8) = pk2(h0, h1);
                        *(uint32_t*)(ol + ni * 8) = pk2(l0, l1);
                    }
                } else {
                    float w = wrow[lr];
                    float* od = g_Y + gr * (size_t)DDIM + n0 + wn * 32 + cp2;
                    #pragma unroll
                    for (int ni = 0; ni < 4; ni++) {
                        float2 v;
                        v.x = w * acc[mi][ni][half * 2 + 0];
                        v.y = w * acc[mi][ni][half * 2 + 1];
                        *(float2*)(od + ni * 8) = v;
                    }
                }
            }
        }
}

// ---------------- combine ----------------
__global__ void combine_kernel(float* __restrict__ out) {
    int idx = blockIdx.x * blockDim.x + threadIdx.x;
    if (idx >= NTOK * (DDIM / 4)) return;
    int n  = idx >> 8;
    int d4 = idx & 255;
    int r0 = g_row_of_token[2 * n + 0];
    int r1 = g_row_of_token[2 * n + 1];
    float4 a = *(const float4*)(g_Y + (size_t)r0 * DDIM + d4 * 4);
    float4 b = *(const float4*)(g_Y + (size_t)r1 * DDIM + d4 * 4);
    float4 o;
    o.x = a.x + b.x; o.y = a.y + b.y; o.z = a.z + b.z; o.w = a.w + b.w;
    ((float4*)out)[idx] = o;
}

// ---------------- launch ----------------
extern "C" void kernel_launch(void* const* d_in, const int* in_sizes, int n_in,
                              void* d_out, int out_size) {
    const float* x  = (const float*)d_in[0];
    const float* Wr = (const float*)d_in[1];
    const float* W1 = (const float*)d_in[2];   // [E][D][F]
    const float* W2 = (const float*)d_in[3];   // [E][F][D]
    float* out = (float*)d_out;

    cudaFuncSetAttribute(moe_gemm_kernel<true>,
                         cudaFuncAttributeMaxDynamicSharedMemorySize, SMEM_BYTES);
    cudaFuncSetAttribute(moe_gemm_kernel<false>,
                         cudaFuncAttributeMaxDynamicSharedMemorySize, SMEM_BYTES);

    zero_kernel<<<1, 32>>>();
    router_kernel<<<64, 256>>>(x, Wr);
    prefix_kernel<<<1, 1>>>();
    dispatch_kernel<<<(NTOK + 255) / 256, 256>>>();
    moe_gemm_kernel<true><<<dim3(NROWS / 128, FDIM / 128, NEXP), 256, SMEM_BYTES>>>(x, W1);
    moe_gemm_kernel<false><<<dim3(NROWS / 128, DDIM / 128, NEXP), 256, SMEM_BYTES>>>(nullptr, W2);
    combine_kernel<<<(NTOK * (DDIM / 4) + 255) / 256, 256>>>(out);
}

// round 8
// speedup vs baseline: 2.1421x; 1.5024x over previous
#include <cuda_runtime.h>
#include <cuda_bf16.h>
#include <math.h>
#include <stdint.h>

#define NTOK 4096   // B*T
#define DDIM 1024
#define FDIM 4096
#define NEXP 8
#define NROWS (NTOK * 2)   // dispatch rows (top-2)

// GEMM tiling: 128x128 CTA tile, K-chunk 16, 2-stage smem double buffer (static)
#define KCH 16
#define APITCH 48                    // 16 bf16 = 32B padded to 48B (odd 16B units)
#define BPITCH 272                   // 128 bf16 = 256B padded to 272B
#define A_TILE (128 * APITCH)        // 6144 per half (hi or lo)
#define B_TILE (KCH * BPITCH)        // 4352 per half
#define STAGE  (2 * A_TILE + 2 * B_TILE)  // 20992

// ---------------- device scratch (~162MB, proven in R7) ----------------
__device__ int   g_count[NEXP];
__device__ int   g_cursor[NEXP];
__device__ int   g_offset[NEXP];
__device__ int   g_topk_idx[NTOK * 2];
__device__ float g_topk_w[NTOK * 2];
__device__ int   g_token_of_row[NROWS];
__device__ float g_w_of_row[NROWS];
__device__ int   g_row_of_token[NROWS];
__device__ __align__(16) __nv_bfloat16 g_Hhi[(size_t)NROWS * FDIM];  // 64 MB
__device__ __align__(16) __nv_bfloat16 g_Hlo[(size_t)NROWS * FDIM];  // 64 MB
__device__ __align__(16) float         g_Y[(size_t)NROWS * DDIM];    // 33.5 MB

// ---------------- helpers ----------------
__device__ __forceinline__ uint32_t smem_u32(const void* p) {
    uint32_t a;
    asm("{ .reg .u64 t; cvta.to.shared.u64 t, %1; cvt.u32.u64 %0, t; }" : "=r"(a) : "l"(p));
    return a;
}
__device__ __forceinline__ void ldm_x4(uint32_t (&r)[4], uint32_t a) {
    asm volatile("ldmatrix.sync.aligned.m8n8.x4.shared.b16 {%0,%1,%2,%3}, [%4];"
                 : "=r"(r[0]), "=r"(r[1]), "=r"(r[2]), "=r"(r[3]) : "r"(a));
}
__device__ __forceinline__ void ldm_x4t(uint32_t (&r)[4], uint32_t a) {
    asm volatile("ldmatrix.sync.aligned.m8n8.x4.trans.shared.b16 {%0,%1,%2,%3}, [%4];"
                 : "=r"(r[0]), "=r"(r[1]), "=r"(r[2]), "=r"(r[3]) : "r"(a));
}
__device__ __forceinline__ void mma16816(float (&d)[4], const uint32_t (&a)[4],
                                         uint32_t b0, uint32_t b1) {
    asm volatile("mma.sync.aligned.m16n8k16.row.col.f32.bf16.bf16.f32 "
                 "{%0,%1,%2,%3}, {%4,%5,%6,%7}, {%8,%9}, {%0,%1,%2,%3};"
                 : "+f"(d[0]), "+f"(d[1]), "+f"(d[2]), "+f"(d[3])
                 : "r"(a[0]), "r"(a[1]), "r"(a[2]), "r"(a[3]), "r"(b0), "r"(b1));
}
__device__ __forceinline__ uint32_t pk2(__nv_bfloat16 a, __nv_bfloat16 b) {
    return (uint32_t)__bfloat16_as_ushort(a) | ((uint32_t)__bfloat16_as_ushort(b) << 16);
}
__device__ __forceinline__ float gelu_exact(float v) {
    return 0.5f * v * (1.0f + erff(v * 0.70710678118654752440f));
}
__device__ __forceinline__ void split8(float4 v0, float4 v1, uint4& hi, uint4& lo) {
    __nv_bfloat16 h0 = __float2bfloat16(v0.x), h1 = __float2bfloat16(v0.y);
    __nv_bfloat16 h2 = __float2bfloat16(v0.z), h3 = __float2bfloat16(v0.w);
    __nv_bfloat16 h4 = __float2bfloat16(v1.x), h5 = __float2bfloat16(v1.y);
    __nv_bfloat16 h6 = __float2bfloat16(v1.z), h7 = __float2bfloat16(v1.w);
    hi.x = pk2(h0, h1); hi.y = pk2(h2, h3); hi.z = pk2(h4, h5); hi.w = pk2(h6, h7);
    lo.x = pk2(__float2bfloat16(v0.x - __bfloat162float(h0)),
               __float2bfloat16(v0.y - __bfloat162float(h1)));
    lo.y = pk2(__float2bfloat16(v0.z - __bfloat162float(h2)),
               __float2bfloat16(v0.w - __bfloat162float(h3)));
    lo.z = pk2(__float2bfloat16(v1.x - __bfloat162float(h4)),
               __float2bfloat16(v1.y - __bfloat162float(h5)));
    lo.w = pk2(__float2bfloat16(v1.z - __bfloat162float(h6)),
               __float2bfloat16(v1.w - __bfloat162float(h7)));
}

// ---------------- K0-K3: routing (unchanged, proven) ----------------
__global__ void zero_kernel() {
    int t = threadIdx.x;
    if (t < NEXP) { g_count[t] = 0; g_cursor[t] = 0; }
}

__global__ void router_kernel(const float* __restrict__ x,
                              const float* __restrict__ Wr) {
    int gwarp  = (blockIdx.x * blockDim.x + threadIdx.x) >> 5;
    int lane   = threadIdx.x & 31;
    int nwarps = (gridDim.x * blockDim.x) >> 5;
    for (int n = gwarp; n < NTOK; n += nwarps) {
        const float* xr = x + (size_t)n * DDIM;
        float acc[NEXP];
        #pragma unroll
        for (int e = 0; e < NEXP; e++) acc[e] = 0.f;
        for (int d = lane; d < DDIM; d += 32) {
            float xv = xr[d];
            const float* wr = Wr + (size_t)d * NEXP;
            float4 w0 = *(const float4*)(wr);
            float4 w1 = *(const float4*)(wr + 4);
            acc[0] = fmaf(xv, w0.x, acc[0]); acc[1] = fmaf(xv, w0.y, acc[1]);
            acc[2] = fmaf(xv, w0.z, acc[2]); acc[3] = fmaf(xv, w0.w, acc[3]);
            acc[4] = fmaf(xv, w1.x, acc[4]); acc[5] = fmaf(xv, w1.y, acc[5]);
            acc[6] = fmaf(xv, w1.z, acc[6]); acc[7] = fmaf(xv, w1.w, acc[7]);
        }
        #pragma unroll
        for (int e = 0; e < NEXP; e++)
            #pragma unroll
            for (int o = 16; o > 0; o >>= 1)
                acc[e] += __shfl_xor_sync(0xFFFFFFFFu, acc[e], o);
        if (lane == 0) {
            int i0 = 0; float v0 = acc[0];
            #pragma unroll
            for (int e = 1; e < NEXP; e++)
                if (acc[e] > v0) { v0 = acc[e]; i0 = e; }
            int i1 = -1; float v1 = -3.4e38f;
            #pragma unroll
            for (int e = 0; e < NEXP; e++)
                if (e != i0 && acc[e] > v1) { v1 = acc[e]; i1 = e; }
            float e1 = __expf(v1 - v0);
            float inv = 1.0f / (1.0f + e1);
            g_topk_idx[2 * n + 0] = i0;
            g_topk_idx[2 * n + 1] = i1;
            g_topk_w[2 * n + 0] = inv;
            g_topk_w[2 * n + 1] = e1 * inv;
            atomicAdd(&g_count[i0], 1);
            atomicAdd(&g_count[i1], 1);
        }
    }
}

__global__ void prefix_kernel() {
    int s = 0;
    for (int e = 0; e < NEXP; e++) { g_offset[e] = s; s += g_count[e]; }
}

__global__ void dispatch_kernel() {
    int n = blockIdx.x * blockDim.x + threadIdx.x;
    if (n >= NTOK) return;
    #pragma unroll
    for (int s = 0; s < 2; s++) {
        int e   = g_topk_idx[2 * n + s];
        int pos = atomicAdd(&g_cursor[e], 1);
        int row = g_offset[e] + pos;
        g_token_of_row[row] = n;
        g_w_of_row[row]     = g_topk_w[2 * n + s];
        g_row_of_token[2 * n + s] = row;
    }
}

// ---------------- GEMM: split-bf16 mma.sync, static smem, 1 sync/chunk ----
// PH1: H(bf16 hi/lo) = gelu(gather(X) @ W1[e]); PH2: Y = w * (H @ W2[e])
template<bool PH1>
__global__ __launch_bounds__(256, 2) void moe_gemm_kernel(const float* __restrict__ Xglob,
                                                          const float* __restrict__ Wglob) {
    constexpr int K  = PH1 ? DDIM : FDIM;
    constexpr int NT = PH1 ? FDIM : DDIM;
    constexpr int NC = K / KCH;

    const int e   = blockIdx.z;
    const int cnt = g_count[e];
    const int m0  = blockIdx.x * 128;
    if (m0 >= cnt) return;
    const int n0  = blockIdx.y * 128;
    const int off = g_offset[e];
    const size_t rowbase = (size_t)off + m0;
    const float* Bsrc = Wglob + (size_t)e * K * NT + n0;

    __shared__ __align__(128) char smbuf[2][STAGE];
    __shared__ int   toks[128];
    __shared__ float wrow[128];

    const int tid  = threadIdx.x;
    const int warp = tid >> 5, lane = tid & 31;
    const int wm = warp & 1, wn = warp >> 1;    // 2x4 warps: 64m x 32n each

    if (tid < 128) {
        int r = m0 + tid;
        if (PH1) toks[tid] = (r < cnt) ? g_token_of_row[off + r] : g_token_of_row[off];
        else     wrow[tid] = (r < cnt) ? g_w_of_row[off + r] : 0.f;
    }
    __syncthreads();

    // loader roles: A 128 rows x 2 segs(8 elems); B 16 k-rows x 16 segs(8 elems)
    const int a_row = tid >> 1, a_seg = tid & 1;
    const int b_k   = tid >> 4, b_seg = tid & 15;

    const float* aptrF = nullptr;
    const __nv_bfloat16 *aptrH = nullptr, *aptrL = nullptr;
    if (PH1) {
        aptrF = Xglob + (size_t)toks[a_row] * DDIM;
    } else {
        size_t ra = rowbase + a_row;
        if (ra >= NROWS) ra = 0;
        aptrH = g_Hhi + ra * (size_t)FDIM;
        aptrL = g_Hlo + ra * (size_t)FDIM;
    }

    // prefetch registers
    float4 pa0, pa1;       // PH1: 8 fp32 of A
    uint4  pah, pal;       // PH2: 8 bf16 hi + 8 bf16 lo of A
    float4 pb0, pb1;       // 8 fp32 of B

    auto prefetch = [&](int kc) {
        if (PH1) {
            pa0 = *(const float4*)(aptrF + kc + a_seg * 8);
            pa1 = *(const float4*)(aptrF + kc + a_seg * 8 + 4);
        } else {
            pah = *(const uint4*)(aptrH + kc + a_seg * 8);
            pal = *(const uint4*)(aptrL + kc + a_seg * 8);
        }
        pb0 = *(const float4*)(Bsrc + (size_t)(kc + b_k) * NT + b_seg * 8);
        pb1 = *(const float4*)(Bsrc + (size_t)(kc + b_k) * NT + b_seg * 8 + 4);
    };
    auto store_stage = [&](int stg) {
        char* dst = smbuf[stg];
        uint4 hi, lo;
        if (PH1) {
            split8(pa0, pa1, hi, lo);
        } else {
            hi = pah; lo = pal;
        }
        *(uint4*)(dst + a_row * APITCH + a_seg * 16) = hi;
        *(uint4*)(dst + A_TILE + a_row * APITCH + a_seg * 16) = lo;
        split8(pb0, pb1, hi, lo);
        *(uint4*)(dst + 2 * A_TILE + b_k * BPITCH + b_seg * 16) = hi;
        *(uint4*)(dst + 2 * A_TILE + B_TILE + b_k * BPITCH + b_seg * 16) = lo;
    };

    prefetch(0);
    store_stage(0);

    float acc[4][4][4];
    #pragma unroll
    for (int i = 0; i < 4; i++)
        #pragma unroll
        for (int j = 0; j < 4; j++)
            #pragma unroll
            for (int q = 0; q < 4; q++) acc[i][j][q] = 0.f;

    const uint32_t smb = smem_u32(smbuf);
    const int lrow = lane & 15;
    const int lk   = lane >> 4;
    const uint32_t aoff = (uint32_t)((wm * 64 + lrow) * APITCH + lk * 16);
    const uint32_t boff = (uint32_t)(2 * A_TILE + lrow * BPITCH + wn * 64 + lk * 16);

    #pragma unroll 1
    for (int c = 0; c < NC; c++) {
        __syncthreads();   // stage c&1 stores visible; stage (c+1)&1 readers done
        if (c + 1 < NC) prefetch((c + 1) * KCH);   // LDG overlaps MMAs below

        uint32_t stb = smb + (uint32_t)((c & 1) * STAGE);
        uint32_t bh[2][4], bl[2][4];
        #pragma unroll
        for (int p = 0; p < 2; p++) {
            uint32_t b = stb + boff + p * 32;
            ldm_x4t(bh[p], b);
            ldm_x4t(bl[p], b + B_TILE);
        }
        #pragma unroll
        for (int mi = 0; mi < 4; mi++) {
            uint32_t ah[4], al[4];
            uint32_t a = stb + aoff + mi * (16 * APITCH);
            ldm_x4(ah, a);
            ldm_x4(al, a + A_TILE);
            #pragma unroll
            for (int ni = 0; ni < 4; ni++) {
                int p = ni >> 1, q = (ni & 1) * 2;
                mma16816(acc[mi][ni], ah, bh[p][q], bh[p][q + 1]);
                mma16816(acc[mi][ni], ah, bl[p][q], bl[p][q + 1]);
                mma16816(acc[mi][ni], al, bh[p][q], bh[p][q + 1]);
            }
        }
        if (c + 1 < NC) store_stage((c + 1) & 1);
    }

    // ---------------- epilogue ----------------
    const int ro  = lane >> 2;
    const int cp2 = (lane & 3) * 2;
    #pragma unroll
    for (int mi = 0; mi < 4; mi++)
        #pragma unroll
        for (int half = 0; half < 2; half++) {
            int lr = wm * 64 + mi * 16 + half * 8 + ro;
            if (m0 + lr < cnt) {
                size_t gr = rowbase + lr;
                if (PH1) {
                    __nv_bfloat16* oh = g_Hhi + gr * (size_t)FDIM + n0 + wn * 32 + cp2;
                    __nv_bfloat16* ol = g_Hlo + gr * (size_t)FDIM + n0 + wn * 32 + cp2;
                    #pragma unroll
                    for (int ni = 0; ni < 4; ni++) {
                        float f0 = gelu_exact(acc[mi][ni][half * 2 + 0]);
                        float f1 = gelu_exact(acc[mi][ni][half * 2 + 1]);
                        __nv_bfloat16 h0 = __float2bfloat16(f0), h1 = __float2bfloat16(f1);
                        __nv_bfloat16 l0 = __float2bfloat16(f0 - __bfloat162float(h0));
                        __nv_bfloat16 l1 = __float2bfloat16(f1 - __bfloat162float(h1));
                        *(uint32_t*)(oh + ni * 8) = pk2(h0, h1);
                        *(uint32_t*)(ol + ni * 8) = pk2(l0, l1);
                    }
                } else {
                    float w = wrow[lr];
                    float* od = g_Y + gr * (size_t)DDIM + n0 + wn * 32 + cp2;
                    #pragma unroll
                    for (int ni = 0; ni < 4; ni++) {
                        float2 v;
                        v.x = w * acc[mi][ni][half * 2 + 0];
                        v.y = w * acc[mi][ni][half * 2 + 1];
                        *(float2*)(od + ni * 8) = v;
                    }
                }
            }
        }
}

// ---------------- combine ----------------
__global__ void combine_kernel(float* __restrict__ out) {
    int idx = blockIdx.x * blockDim.x + threadIdx.x;
    if (idx >= NTOK * (DDIM / 4)) return;
    int n  = idx >> 8;
    int d4 = idx & 255;
    int r0 = g_row_of_token[2 * n + 0];
    int r1 = g_row_of_token[2 * n + 1];
    float4 a = *(const float4*)(g_Y + (size_t)r0 * DDIM + d4 * 4);
    float4 b = *(const float4*)(g_Y + (size_t)r1 * DDIM + d4 * 4);
    float4 o;
    o.x = a.x + b.x; o.y = a.y + b.y; o.z = a.z + b.z; o.w = a.w + b.w;
    ((float4*)out)[idx] = o;
}

// ---------------- launch ----------------
extern "C" void kernel_launch(void* const* d_in, const int* in_sizes, int n_in,
                              void* d_out, int out_size) {
    const float* x  = (const float*)d_in[0];
    const float* Wr = (const float*)d_in[1];
    const float* W1 = (const float*)d_in[2];   // [E][D][F]
    const float* W2 = (const float*)d_in[3];   // [E][F][D]
    float* out = (float*)d_out;

    zero_kernel<<<1, 32>>>();
    router_kernel<<<64, 256>>>(x, Wr);
    prefix_kernel<<<1, 1>>>();
    dispatch_kernel<<<(NTOK + 255) / 256, 256>>>();
    moe_gemm_kernel<true><<<dim3(NROWS / 128, FDIM / 128, NEXP), 256>>>(x, W1);
    moe_gemm_kernel<false><<<dim3(NROWS / 128, DDIM / 128, NEXP), 256>>>(nullptr, W2);
    combine_kernel<<<(NTOK * (DDIM / 4) + 255) / 256, 256>>>(out);
}

// round 9
// speedup vs baseline: 2.1639x; 1.0102x over previous
#include <cuda_runtime.h>
#include <cuda_bf16.h>
#include <math.h>
#include <stdint.h>

#define NTOK 4096   // B*T
#define DDIM 1024
#define FDIM 4096
#define NEXP 8
#define NROWS (NTOK * 2)   // dispatch rows (top-2)

// GEMM tiling: 128x128 CTA tile, K-chunk 16, 2-stage smem double buffer (static)
#define KCH 16
#define APITCH 48                    // 16 bf16 = 32B padded to 48B (odd 16B units)
#define BPITCH 272                   // 128 bf16 = 256B padded to 272B
#define A_TILE (128 * APITCH)        // 6144 per half (hi or lo)
#define B_TILE (KCH * BPITCH)        // 4352 per half
#define STAGE  (2 * A_TILE + 2 * B_TILE)  // 20992

// ---------------- device scratch (~210MB) ----------------
__device__ int   g_count[NEXP];
__device__ int   g_cursor[NEXP];
__device__ int   g_offset[NEXP];
__device__ int   g_topk_idx[NTOK * 2];
__device__ float g_topk_w[NTOK * 2];
__device__ int   g_token_of_row[NROWS];
__device__ float g_w_of_row[NROWS];
__device__ int   g_row_of_token[NROWS];
__device__ __align__(16) __nv_bfloat16 g_Xhi[(size_t)NROWS * DDIM];  // 16 MB
__device__ __align__(16) __nv_bfloat16 g_Xlo[(size_t)NROWS * DDIM];  // 16 MB
__device__ __align__(16) __nv_bfloat16 g_Hhi[(size_t)NROWS * FDIM];  // 64 MB
__device__ __align__(16) __nv_bfloat16 g_Hlo[(size_t)NROWS * FDIM];  // 64 MB
__device__ __align__(16) float         g_Y[(size_t)NROWS * DDIM];    // 33.5 MB

// ---------------- helpers ----------------
__device__ __forceinline__ uint32_t smem_u32(const void* p) {
    uint32_t a;
    asm("{ .reg .u64 t; cvta.to.shared.u64 t, %1; cvt.u32.u64 %0, t; }" : "=r"(a) : "l"(p));
    return a;
}
__device__ __forceinline__ void ldm_x4(uint32_t (&r)[4], uint32_t a) {
    asm volatile("ldmatrix.sync.aligned.m8n8.x4.shared.b16 {%0,%1,%2,%3}, [%4];"
                 : "=r"(r[0]), "=r"(r[1]), "=r"(r[2]), "=r"(r[3]) : "r"(a));
}
__device__ __forceinline__ void ldm_x4t(uint32_t (&r)[4], uint32_t a) {
    asm volatile("ldmatrix.sync.aligned.m8n8.x4.trans.shared.b16 {%0,%1,%2,%3}, [%4];"
                 : "=r"(r[0]), "=r"(r[1]), "=r"(r[2]), "=r"(r[3]) : "r"(a));
}
__device__ __forceinline__ void mma16816(float (&d)[4], const uint32_t (&a)[4],
                                         uint32_t b0, uint32_t b1) {
    asm volatile("mma.sync.aligned.m16n8k16.row.col.f32.bf16.bf16.f32 "
                 "{%0,%1,%2,%3}, {%4,%5,%6,%7}, {%8,%9}, {%0,%1,%2,%3};"
                 : "+f"(d[0]), "+f"(d[1]), "+f"(d[2]), "+f"(d[3])
                 : "r"(a[0]), "r"(a[1]), "r"(a[2]), "r"(a[3]), "r"(b0), "r"(b1));
}
__device__ __forceinline__ uint32_t pk2(__nv_bfloat16 a, __nv_bfloat16 b) {
    return (uint32_t)__bfloat16_as_ushort(a) | ((uint32_t)__bfloat16_as_ushort(b) << 16);
}
__device__ __forceinline__ float gelu_exact(float v) {
    return 0.5f * v * (1.0f + erff(v * 0.70710678118654752440f));
}
__device__ __forceinline__ void split8(float4 v0, float4 v1, uint4& hi, uint4& lo) {
    __nv_bfloat16 h0 = __float2bfloat16(v0.x), h1 = __float2bfloat16(v0.y);
    __nv_bfloat16 h2 = __float2bfloat16(v0.z), h3 = __float2bfloat16(v0.w);
    __nv_bfloat16 h4 = __float2bfloat16(v1.x), h5 = __float2bfloat16(v1.y);
    __nv_bfloat16 h6 = __float2bfloat16(v1.z), h7 = __float2bfloat16(v1.w);
    hi.x = pk2(h0, h1); hi.y = pk2(h2, h3); hi.z = pk2(h4, h5); hi.w = pk2(h6, h7);
    lo.x = pk2(__float2bfloat16(v0.x - __bfloat162float(h0)),
               __float2bfloat16(v0.y - __bfloat162float(h1)));
    lo.y = pk2(__float2bfloat16(v0.z - __bfloat162float(h2)),
               __float2bfloat16(v0.w - __bfloat162float(h3)));
    lo.z = pk2(__float2bfloat16(v1.x - __bfloat162float(h4)),
               __float2bfloat16(v1.y - __bfloat162float(h5)));
    lo.w = pk2(__float2bfloat16(v1.z - __bfloat162float(h6)),
               __float2bfloat16(v1.w - __bfloat162float(h7)));
}

// ---------------- K0-K3: routing (unchanged, proven) ----------------
__global__ void zero_kernel() {
    int t = threadIdx.x;
    if (t < NEXP) { g_count[t] = 0; g_cursor[t] = 0; }
}

__global__ void router_kernel(const float* __restrict__ x,
                              const float* __restrict__ Wr) {
    int gwarp  = (blockIdx.x * blockDim.x + threadIdx.x) >> 5;
    int lane   = threadIdx.x & 31;
    int nwarps = (gridDim.x * blockDim.x) >> 5;
    for (int n = gwarp; n < NTOK; n += nwarps) {
        const float* xr = x + (size_t)n * DDIM;
        float acc[NEXP];
        #pragma unroll
        for (int e = 0; e < NEXP; e++) acc[e] = 0.f;
        for (int d = lane; d < DDIM; d += 32) {
            float xv = xr[d];
            const float* wr = Wr + (size_t)d * NEXP;
            float4 w0 = *(const float4*)(wr);
            float4 w1 = *(const float4*)(wr + 4);
            acc[0] = fmaf(xv, w0.x, acc[0]); acc[1] = fmaf(xv, w0.y, acc[1]);
            acc[2] = fmaf(xv, w0.z, acc[2]); acc[3] = fmaf(xv, w0.w, acc[3]);
            acc[4] = fmaf(xv, w1.x, acc[4]); acc[5] = fmaf(xv, w1.y, acc[5]);
            acc[6] = fmaf(xv, w1.z, acc[6]); acc[7] = fmaf(xv, w1.w, acc[7]);
        }
        #pragma unroll
        for (int e = 0; e < NEXP; e++)
            #pragma unroll
            for (int o = 16; o > 0; o >>= 1)
                acc[e] += __shfl_xor_sync(0xFFFFFFFFu, acc[e], o);
        if (lane == 0) {
            int i0 = 0; float v0 = acc[0];
            #pragma unroll
            for (int e = 1; e < NEXP; e++)
                if (acc[e] > v0) { v0 = acc[e]; i0 = e; }
            int i1 = -1; float v1 = -3.4e38f;
            #pragma unroll
            for (int e = 0; e < NEXP; e++)
                if (e != i0 && acc[e] > v1) { v1 = acc[e]; i1 = e; }
            float e1 = __expf(v1 - v0);
            float inv = 1.0f / (1.0f + e1);
            g_topk_idx[2 * n + 0] = i0;
            g_topk_idx[2 * n + 1] = i1;
            g_topk_w[2 * n + 0] = inv;
            g_topk_w[2 * n + 1] = e1 * inv;
            atomicAdd(&g_count[i0], 1);
            atomicAdd(&g_count[i1], 1);
        }
    }
}

__global__ void prefix_kernel() {
    int s = 0;
    for (int e = 0; e < NEXP; e++) { g_offset[e] = s; s += g_count[e]; }
}

__global__ void dispatch_kernel() {
    int n = blockIdx.x * blockDim.x + threadIdx.x;
    if (n >= NTOK) return;
    #pragma unroll
    for (int s = 0; s < 2; s++) {
        int e   = g_topk_idx[2 * n + s];
        int pos = atomicAdd(&g_cursor[e], 1);
        int row = g_offset[e] + pos;
        g_token_of_row[row] = n;
        g_w_of_row[row]     = g_topk_w[2 * n + s];
        g_row_of_token[2 * n + s] = row;
    }
}

// ---------------- K4: gather + split X -> bf16 hi/lo (expert-compact) -----
__global__ void gather_split_x_kernel(const float* __restrict__ x) {
    int r = blockIdx.x;
    int t = g_token_of_row[r];
    float4 v = ((const float4*)(x + (size_t)t * DDIM))[threadIdx.x];
    __nv_bfloat16 h0 = __float2bfloat16(v.x), h1 = __float2bfloat16(v.y);
    __nv_bfloat16 h2 = __float2bfloat16(v.z), h3 = __float2bfloat16(v.w);
    __nv_bfloat16 l0 = __float2bfloat16(v.x - __bfloat162float(h0));
    __nv_bfloat16 l1 = __float2bfloat16(v.y - __bfloat162float(h1));
    __nv_bfloat16 l2 = __float2bfloat16(v.z - __bfloat162float(h2));
    __nv_bfloat16 l3 = __float2bfloat16(v.w - __bfloat162float(h3));
    ((uint2*)(g_Xhi + (size_t)r * DDIM))[threadIdx.x] = make_uint2(pk2(h0, h1), pk2(h2, h3));
    ((uint2*)(g_Xlo + (size_t)r * DDIM))[threadIdx.x] = make_uint2(pk2(l0, l1), pk2(l2, l3));
}

// ---------------- GEMM: split-bf16 mma.sync ----------------
// PH1: H(bf16 hi/lo) = gelu(Xsplit @ W1[e]), grid (m, n, e)
// PH2: Y = w * (Hsplit @ W2[e]),             grid (n, m, e)  [n fastest: H reuse]
template<bool PH1>
__global__ __launch_bounds__(256, 2) void moe_gemm_kernel(const float* __restrict__ Wglob) {
    constexpr int K  = PH1 ? DDIM : FDIM;
    constexpr int NT = PH1 ? FDIM : DDIM;
    constexpr int NC = K / KCH;

    const int e   = blockIdx.z;
    const int cnt = g_count[e];
    const int m0  = (PH1 ? blockIdx.x : blockIdx.y) * 128;
    if (m0 >= cnt) return;
    const int n0  = (PH1 ? blockIdx.y : blockIdx.x) * 128;
    const int off = g_offset[e];
    const size_t rowbase = (size_t)off + m0;
    const float* Bsrc = Wglob + (size_t)e * K * NT + n0;

    __shared__ __align__(128) char smbuf[2][STAGE];
    __shared__ float wrow[128];

    const int tid  = threadIdx.x;
    const int warp = tid >> 5, lane = tid & 31;
    const int wm = warp & 1, wn = warp >> 1;    // 2x4 warps: 64m x 32n each

    if (!PH1 && tid < 128) {
        int r = m0 + tid;
        wrow[tid] = (r < cnt) ? g_w_of_row[off + r] : 0.f;
    }

    // loader roles: A 128 rows x 2 segs(8 elems); B 16 k-rows x 16 segs(8 elems)
    const int a_row = tid >> 1, a_seg = tid & 1;
    const int b_k   = tid >> 4, b_seg = tid & 15;

    size_t ra = rowbase + a_row;
    if (ra >= NROWS) ra = 0;   // clamp (values discarded via epilogue bounds)
    const __nv_bfloat16* aptrH = (PH1 ? g_Xhi : g_Hhi) + ra * (size_t)K;
    const __nv_bfloat16* aptrL = (PH1 ? g_Xlo : g_Hlo) + ra * (size_t)K;

    // prefetch registers (A pre-split bf16; B fp32)
    uint4  pah, pal;
    float4 pb0, pb1;
    auto prefetch = [&](int kc) {
        pah = *(const uint4*)(aptrH + kc + a_seg * 8);
        pal = *(const uint4*)(aptrL + kc + a_seg * 8);
        pb0 = *(const float4*)(Bsrc + (size_t)(kc + b_k) * NT + b_seg * 8);
        pb1 = *(const float4*)(Bsrc + (size_t)(kc + b_k) * NT + b_seg * 8 + 4);
    };
    auto store_stage = [&](int stg) {
        char* dst = smbuf[stg];
        *(uint4*)(dst + a_row * APITCH + a_seg * 16) = pah;
        *(uint4*)(dst + A_TILE + a_row * APITCH + a_seg * 16) = pal;
        uint4 hi, lo;
        split8(pb0, pb1, hi, lo);
        *(uint4*)(dst + 2 * A_TILE + b_k * BPITCH + b_seg * 16) = hi;
        *(uint4*)(dst + 2 * A_TILE + B_TILE + b_k * BPITCH + b_seg * 16) = lo;
    };

    prefetch(0);
    store_stage(0);

    float acc[4][4][4];
    #pragma unroll
    for (int i = 0; i < 4; i++)
        #pragma unroll
        for (int j = 0; j < 4; j++)
            #pragma unroll
            for (int q = 0; q < 4; q++) acc[i][j][q] = 0.f;

    const uint32_t smb = smem_u32(smbuf);
    const int lrow = lane & 15;
    const int lk   = lane >> 4;
    const uint32_t aoff = (uint32_t)((wm * 64 + lrow) * APITCH + lk * 16);
    const uint32_t boff = (uint32_t)(2 * A_TILE + lrow * BPITCH + wn * 64 + lk * 16);

    #pragma unroll 1
    for (int c = 0; c < NC; c++) {
        if (c + 1 < NC) prefetch((c + 1) * KCH);   // issue LDG before barrier
        __syncthreads();   // stage c&1 stores visible; stage (c+1)&1 readers done

        uint32_t stb = smb + (uint32_t)((c & 1) * STAGE);
        uint32_t bh[2][4], bl[2][4];
        #pragma unroll
        for (int p = 0; p < 2; p++) {
            uint32_t b = stb + boff + p * 32;
            ldm_x4t(bh[p], b);
            ldm_x4t(bl[p], b + B_TILE);
        }
        #pragma unroll
        for (int mi = 0; mi < 4; mi++) {
            uint32_t ah[4], al[4];
            uint32_t a = stb + aoff + mi * (16 * APITCH);
            ldm_x4(ah, a);
            ldm_x4(al, a + A_TILE);
            #pragma unroll
            for (int ni = 0; ni < 4; ni++) {
                int p = ni >> 1, q = (ni & 1) * 2;
                mma16816(acc[mi][ni], ah, bh[p][q], bh[p][q + 1]);
                mma16816(acc[mi][ni], ah, bl[p][q], bl[p][q + 1]);
                mma16816(acc[mi][ni], al, bh[p][q], bh[p][q + 1]);
            }
        }
        if (c + 1 < NC) store_stage((c + 1) & 1);
    }

    // ---------------- epilogue ----------------
    const int ro  = lane >> 2;
    const int cp2 = (lane & 3) * 2;
    #pragma unroll
    for (int mi = 0; mi < 4; mi++)
        #pragma unroll
        for (int half = 0; half < 2; half++) {
            int lr = wm * 64 + mi * 16 + half * 8 + ro;
            if (m0 + lr < cnt) {
                size_t gr = rowbase + lr;
                if (PH1) {
                    __nv_bfloat16* oh = g_Hhi + gr * (size_t)FDIM + n0 + wn * 32 + cp2;
                    __nv_bfloat16* ol = g_Hlo + gr * (size_t)FDIM + n0 + wn * 32 + cp2;
                    #pragma unroll
                    for (int ni = 0; ni < 4; ni++) {
                        float f0 = gelu_exact(acc[mi][ni][half * 2 + 0]);
                        float f1 = gelu_exact(acc[mi][ni][half * 2 + 1]);
                        __nv_bfloat16 h0 = __float2bfloat16(f0), h1 = __float2bfloat16(f1);
                        __nv_bfloat16 l0 = __float2bfloat16(f0 - __bfloat162float(h0));
                        __nv_bfloat16 l1 = __float2bfloat16(f1 - __bfloat162float(h1));
                        *(uint32_t*)(oh + ni * 8) = pk2(h0, h1);
                        *(uint32_t*)(ol + ni * 8) = pk2(l0, l1);
                    }
                } else {
                    float w = wrow[lr];
                    float* od = g_Y + gr * (size_t)DDIM + n0 + wn * 32 + cp2;
                    #pragma unroll
                    for (int ni = 0; ni < 4; ni++) {
                        float2 v;
                        v.x = w * acc[mi][ni][half * 2 + 0];
                        v.y = w * acc[mi][ni][half * 2 + 1];
                        *(float2*)(od + ni * 8) = v;
                    }
                }
            }
        }
}

// ---------------- combine ----------------
__global__ void combine_kernel(float* __restrict__ out) {
    int idx = blockIdx.x * blockDim.x + threadIdx.x;
    if (idx >= NTOK * (DDIM / 4)) return;
    int n  = idx >> 8;
    int d4 = idx & 255;
    int r0 = g_row_of_token[2 * n + 0];
    int r1 = g_row_of_token[2 * n + 1];
    float4 a = *(const float4*)(g_Y + (size_t)r0 * DDIM + d4 * 4);
    float4 b = *(const float4*)(g_Y + (size_t)r1 * DDIM + d4 * 4);
    float4 o;
    o.x = a.x + b.x; o.y = a.y + b.y; o.z = a.z + b.z; o.w = a.w + b.w;
    ((float4*)out)[idx] = o;
}

// ---------------- launch ----------------
extern "C" void kernel_launch(void* const* d_in, const int* in_sizes, int n_in,
                              void* d_out, int out_size) {
    const float* x  = (const float*)d_in[0];
    const float* Wr = (const float*)d_in[1];
    const float* W1 = (const float*)d_in[2];   // [E][D][F]
    const float* W2 = (const float*)d_in[3];   // [E][F][D]
    float* out = (float*)d_out;

    zero_kernel<<<1, 32>>>();
    router_kernel<<<64, 256>>>(x, Wr);
    prefix_kernel<<<1, 1>>>();
    dispatch_kernel<<<(NTOK + 255) / 256, 256>>>();
    gather_split_x_kernel<<<NROWS, 256>>>(x);
    moe_gemm_kernel<true><<<dim3(NROWS / 128, FDIM / 128, NEXP), 256>>>(W1);
    moe_gemm_kernel<false><<<dim3(DDIM / 128, NROWS / 128, NEXP), 256>>>(W2);
    combine_kernel<<<(NTOK * (DDIM / 4) + 255) / 256, 256>>>(out);
}